// round 11
// baseline (speedup 1.0000x reference)
#include <cuda_runtime.h>
#include <cuda_bf16.h>

#define NUM_GRAPHS  2048
#define MAX_ATOMS   200000
#define THREADS     256
#define PACK_BLOCKS 296   // = 2*148; __launch_bounds__(,2) guarantees residency

// Packed per-atom tag: (batch << 4) | z.  batch < 2048 (11 bits), z in 1..10 (4 bits).
// All state below is zero at kernel_launch entry (zero-init + self-reset each launch).
__device__ unsigned short g_bz[MAX_ATOMS];
__device__ int g_cnt[NUM_GRAPHS];   // running atom counts per graph
__device__ int g_maxd;              // max graph size (prefilter radius)
__device__ int g_done;              // pack-phase release counter
__device__ int g_ready;             // post-barrier ticket for state reset

// Per-edge body: register-only prefilter |s-d| < D, then exact tag check,
// then rare-path physics (~0.15% of edges pass the prefilter).
// Tags via __ldcg (L2-coherent: written earlier in this same launch).
#define EDGE_BODY(s, d)                                                        \
    do {                                                                       \
        if (abs((s) - (d)) < D) {                                              \
            unsigned short bs = __ldcg(&g_bz[(s)]);                            \
            unsigned short bd = __ldcg(&g_bz[(d)]);                            \
            if ((bs >> 4) == (bd >> 4)) {                                      \
                float dx = __ldg(&pos[3 * (s) + 0]) - __ldg(&pos[3 * (d) + 0]);\
                float dy = __ldg(&pos[3 * (s) + 1]) - __ldg(&pos[3 * (d) + 1]);\
                float dz = __ldg(&pos[3 * (s) + 2]) - __ldg(&pos[3 * (d) + 2]);\
                float d2 = dx * dx + dy * dy + dz * dz;                        \
                if (d2 <= 9.0f) {                                              \
                    float dist = fmaxf(sqrtf(d2), 1e-9f);                      \
                    float dau  = dist * 1.8897261258369282f;                   \
                    int zs = bs & 15, zd = bd & 15;                            \
                    float at  = sqrtf(__ldg(&arep[zs]) * __ldg(&arep[zd]));    \
                    float rep = __ldg(&zeff[zs]) * __ldg(&zeff[zd]) *          \
                                expf(-at * dau * sqrtf(dau)) / dau;            \
                    atomicAdd(&out[bs >> 4], rep * 627.5094740630558f);        \
                }                                                              \
            }                                                                  \
        }                                                                      \
    } while (0)

__global__ void __launch_bounds__(THREADS, 2)
fused_kernel(const float* __restrict__ pos,
             const float* __restrict__ arep,
             const float* __restrict__ zeff,
             const int*   __restrict__ z,
             const int*   __restrict__ batch,
             const int*   __restrict__ src_idx,
             const int*   __restrict__ dst_idx,
             float*       __restrict__ out,
             int out_n,
             int n_atoms,
             int n_quads,    // number of 4-edge quads
             int n_rem)      // leftover edges (< 4)
{
    __shared__ int s_D;
    __shared__ int s_last;

    // ---- Phase 1: blocks 0..PACK_BLOCKS-1 pack tags + zero out + maxd ----
    if (blockIdx.x < PACK_BLOCKS) {
        for (int i = blockIdx.x * THREADS + threadIdx.x; i < out_n;
             i += PACK_BLOCKS * THREADS)
            out[i] = 0.0f;
        int rc = 0;
        for (int i = blockIdx.x * THREADS + threadIdx.x; i < n_atoms;
             i += PACK_BLOCKS * THREADS) {
            int b = batch[i];
            g_bz[i] = (unsigned short)((b << 4) | z[i]);
            // running-count trick: max running count == max graph size
            rc = max(rc, atomicAdd(&g_cnt[b], 1) + 1);
        }
        #pragma unroll
        for (int off = 16; off > 0; off >>= 1)
            rc = max(rc, __shfl_down_sync(0xffffffffu, rc, off));
        if ((threadIdx.x & 31) == 0 && rc > 0)
            atomicMax(&g_maxd, rc);
        __syncthreads();                    // all warps' stores+atomics issued
        if (threadIdx.x == 0) {
            __threadfence();                // release tags + maxd
            atomicAdd(&g_done, 1);
        }
    }

    // ---- Barrier: wait for all pack blocks, read D, join reset ticket ----
    if (threadIdx.x == 0) {
        while (*(volatile int*)&g_done < PACK_BLOCKS) __nanosleep(128);
        s_D = *(volatile int*)&g_maxd;      // L2-coherent read
        int arrived = atomicAdd(&g_ready, 1);
        s_last = (arrived == (int)gridDim.x - 1);
    }
    __syncthreads();
    const int D = s_D > 0 ? s_D : 1;        // same-graph => |s-d| < D (batch sorted)

    // Last block (all others have read g_maxd) restores zero state for replay.
    if (s_last) {
        for (int i = threadIdx.x; i < NUM_GRAPHS; i += THREADS) g_cnt[i] = 0;
        if (threadIdx.x == 0) { g_maxd = 0; g_done = 0; g_ready = 0; }
    }

    // ---- Phase 2: edge stream, 4 edges/thread (round-4 proven config) ----
    int t = blockIdx.x * blockDim.x + threadIdx.x;
    if (t < n_quads) {
        int4 s4 = ((const int4*)src_idx)[t];
        int4 d4 = ((const int4*)dst_idx)[t];
        EDGE_BODY(s4.x, d4.x);
        EDGE_BODY(s4.y, d4.y);
        EDGE_BODY(s4.z, d4.z);
        EDGE_BODY(s4.w, d4.w);
    }

    // Scalar tail (edges not covered by quads)
    if (blockIdx.x == 0 && (int)threadIdx.x < n_rem) {
        int e = n_quads * 4 + threadIdx.x;
        int s = src_idx[e];
        int d = dst_idx[e];
        EDGE_BODY(s, d);
    }
}

extern "C" void kernel_launch(void* const* d_in, const int* in_sizes, int n_in,
                              void* d_out, int out_size) {
    const float* pos        = (const float*)d_in[0];
    const float* arep       = (const float*)d_in[1];
    const float* zeff       = (const float*)d_in[2];
    const int*   z          = (const int*)d_in[3];
    const int*   edge_index = (const int*)d_in[4];
    const int*   batch      = (const int*)d_in[5];
    float*       out        = (float*)d_out;

    int n_atoms = in_sizes[3];
    int n_edges = in_sizes[4] / 2;
    const int* src_idx = edge_index;
    const int* dst_idx = edge_index + n_edges;

    int n_quads = n_edges / 4;
    int n_rem   = n_edges - n_quads * 4;
    int blocks  = (n_quads + THREADS - 1) / THREADS;
    if (blocks < PACK_BLOCKS) blocks = PACK_BLOCKS;

    fused_kernel<<<blocks, THREADS>>>(pos, arep, zeff, z, batch,
                                      src_idx, dst_idx, out,
                                      out_size, n_atoms, n_quads, n_rem);
}

// round 14
// speedup vs baseline: 1.2832x; 1.2832x over previous
#include <cuda_runtime.h>
#include <cuda_bf16.h>

#define NUM_GRAPHS 2048
#define MAX_ATOMS  200000
#define THREADS    256

// Packed per-atom tag: (batch << 4) | z.  batch < 2048 (11 bits), z in 1..10 (4 bits).
// g_cnt/g_maxd/g_ready are zero at every kernel_launch entry (zero-init once,
// then restored by the edge kernel's last block on each launch).
__device__ unsigned short g_bz[MAX_ATOMS];
__device__ int g_cnt[NUM_GRAPHS];   // running atom counts per graph
__device__ int g_maxd;              // max graph size (prefilter radius)
__device__ int g_ready;             // edge-kernel arrival ticket (for state reset)

// Kernel 1: zero output + pack tags + max graph size.
// Running-count trick: max over i of (running count of batch[i]) == max graph size.
// 4 atoms/thread via int4 loads (z and batch are int32 arrays).
__global__ void pack_tags_kernel(const int* __restrict__ z,
                                 const int* __restrict__ batch,
                                 float* __restrict__ out, int out_n,
                                 int n_quads,    // n_atoms/4
                                 int n_atoms) {
    int t = blockIdx.x * blockDim.x + threadIdx.x;
    // zero output (2048 floats) from the first blocks
    for (int i = t; i < out_n; i += gridDim.x * blockDim.x) out[i] = 0.0f;

    int rc = 0;
    if (t < n_quads) {
        int4 b4 = ((const int4*)batch)[t];
        int4 z4 = ((const int4*)z)[t];
        rc = max(rc, atomicAdd(&g_cnt[b4.x], 1) + 1);
        rc = max(rc, atomicAdd(&g_cnt[b4.y], 1) + 1);
        rc = max(rc, atomicAdd(&g_cnt[b4.z], 1) + 1);
        rc = max(rc, atomicAdd(&g_cnt[b4.w], 1) + 1);
        ushort4 tag;
        tag.x = (unsigned short)((b4.x << 4) | z4.x);
        tag.y = (unsigned short)((b4.y << 4) | z4.y);
        tag.z = (unsigned short)((b4.z << 4) | z4.z);
        tag.w = (unsigned short)((b4.w << 4) | z4.w);
        ((ushort4*)g_bz)[t] = tag;
    }
    // tail atoms (n_atoms % 4)
    int e = n_quads * 4 + t;
    if (t < (n_atoms - n_quads * 4)) {
        int b = batch[e];
        g_bz[e] = (unsigned short)((b << 4) | z[e]);
        rc = max(rc, atomicAdd(&g_cnt[b], 1) + 1);
    }
    #pragma unroll
    for (int off = 16; off > 0; off >>= 1)
        rc = max(rc, __shfl_down_sync(0xffffffffu, rc, off));
    if ((threadIdx.x & 31) == 0 && rc > 0)
        atomicMax(&g_maxd, rc);
}

// Per-edge body: register-only prefilter |s-d| < D, then exact tag check,
// then rare-path physics (~0.15% of edges pass the prefilter).
#define EDGE_BODY(s, d)                                                        \
    do {                                                                       \
        if (abs((s) - (d)) < D) {                                              \
            unsigned short bs = __ldg(&g_bz[(s)]);                             \
            unsigned short bd = __ldg(&g_bz[(d)]);                             \
            if ((bs >> 4) == (bd >> 4)) {                                      \
                float dx = __ldg(&pos[3 * (s) + 0]) - __ldg(&pos[3 * (d) + 0]);\
                float dy = __ldg(&pos[3 * (s) + 1]) - __ldg(&pos[3 * (d) + 1]);\
                float dz = __ldg(&pos[3 * (s) + 2]) - __ldg(&pos[3 * (d) + 2]);\
                float d2 = dx * dx + dy * dy + dz * dz;                        \
                if (d2 <= 9.0f) {                                              \
                    float dist = fmaxf(sqrtf(d2), 1e-9f);                      \
                    float dau  = dist * 1.8897261258369282f;                   \
                    int zs = bs & 15, zd = bd & 15;                            \
                    float at  = sqrtf(__ldg(&arep[zs]) * __ldg(&arep[zd]));    \
                    float rep = __ldg(&zeff[zs]) * __ldg(&zeff[zd]) *          \
                                expf(-at * dau * sqrtf(dau)) / dau;            \
                    atomicAdd(&out[bs >> 4], rep * 627.5094740630558f);        \
                }                                                              \
            }                                                                  \
        }                                                                      \
    } while (0)

// Kernel 2: main edge stream, 4 edges/thread (round-4 proven config),
// streaming (.cs) loads for the never-reused edge index data.
// Last-arriving block resets device state for the next graph replay.
__global__ void __launch_bounds__(THREADS)
repulsion_kernel(const float* __restrict__ pos,
                 const float* __restrict__ arep,
                 const float* __restrict__ zeff,
                 const int*   __restrict__ src_idx,
                 const int*   __restrict__ dst_idx,
                 float*       __restrict__ out,
                 int n_quads,    // number of 4-edge quads
                 int n_rem)      // leftover edges (< 4)
{
    __shared__ int s_D;
    __shared__ int s_last;

    // Read D BEFORE joining the ticket, so the resetter can never clobber
    // g_maxd before this block has read it.
    if (threadIdx.x == 0) {
        s_D = g_maxd;
        int arrived = atomicAdd(&g_ready, 1);
        s_last = (arrived == (int)gridDim.x - 1);
    }
    __syncthreads();
    const int D = s_D > 0 ? s_D : 1;   // same-graph => |src-dst| < D (batch sorted)

    // Last block restores the zero state for the next replay.
    if (s_last) {
        for (int i = threadIdx.x; i < NUM_GRAPHS; i += THREADS) g_cnt[i] = 0;
        if (threadIdx.x == 0) { g_maxd = 0; g_ready = 0; }
    }

    int t = blockIdx.x * blockDim.x + threadIdx.x;
    if (t < n_quads) {
        // evict-first streaming loads: edge data is never reused
        int4 s4 = __ldcs(&((const int4*)src_idx)[t]);
        int4 d4 = __ldcs(&((const int4*)dst_idx)[t]);
        EDGE_BODY(s4.x, d4.x);
        EDGE_BODY(s4.y, d4.y);
        EDGE_BODY(s4.z, d4.z);
        EDGE_BODY(s4.w, d4.w);
    }

    // Scalar tail (edges not covered by quads)
    if (blockIdx.x == 0 && (int)threadIdx.x < n_rem) {
        int e = n_quads * 4 + threadIdx.x;
        int s = src_idx[e];
        int d = dst_idx[e];
        EDGE_BODY(s, d);
    }
}

extern "C" void kernel_launch(void* const* d_in, const int* in_sizes, int n_in,
                              void* d_out, int out_size) {
    const float* pos        = (const float*)d_in[0];
    const float* arep       = (const float*)d_in[1];
    const float* zeff       = (const float*)d_in[2];
    const int*   z          = (const int*)d_in[3];
    const int*   edge_index = (const int*)d_in[4];
    const int*   batch      = (const int*)d_in[5];
    float*       out        = (float*)d_out;

    int n_atoms = in_sizes[3];
    int n_edges = in_sizes[4] / 2;
    const int* src_idx = edge_index;
    const int* dst_idx = edge_index + n_edges;

    // 1) pack tags + zero output + max graph size
    int a_quads = n_atoms / 4;
    int pack_blocks = (a_quads + THREADS - 1) / THREADS;
    if (pack_blocks < 1) pack_blocks = 1;
    pack_tags_kernel<<<pack_blocks, THREADS>>>(z, batch, out, out_size,
                                               a_quads, n_atoms);

    // 2) main edge stream (4 edges/thread)
    int n_quads = n_edges / 4;
    int n_rem   = n_edges - n_quads * 4;
    int blocks  = (n_quads + THREADS - 1) / THREADS;
    if (blocks < 1) blocks = 1;
    repulsion_kernel<<<blocks, THREADS>>>(pos, arep, zeff, src_idx, dst_idx,
                                          out, n_quads, n_rem);
}

// round 15
// speedup vs baseline: 1.3372x; 1.0420x over previous
#include <cuda_runtime.h>
#include <cuda_bf16.h>

#define NUM_GRAPHS 2048
#define MAX_ATOMS  200000
#define THREADS    256

// Packed per-atom tag: (batch << 4) | z.  batch < 2048 (11 bits), z in 1..10 (4 bits).
// g_cnt/g_maxd/g_ready are zero at every kernel_launch entry (zero-init once,
// then restored by the edge kernel's last block on each launch).
__device__ unsigned short g_bz[MAX_ATOMS];
__device__ int g_cnt[NUM_GRAPHS];   // running atom counts per graph
__device__ int g_maxd;              // max graph size (prefilter radius)
__device__ int g_ready;             // edge-kernel arrival ticket (for state reset)

// Kernel 1: zero output + pack tags + max graph size.
// Running-count trick: max over i of (running count of batch[i]) == max graph size.
// 4 atoms/thread via int4 loads (z and batch are int32 arrays).
__global__ void pack_tags_kernel(const int* __restrict__ z,
                                 const int* __restrict__ batch,
                                 float* __restrict__ out, int out_n,
                                 int n_quads,    // n_atoms/4
                                 int n_atoms) {
    int t = blockIdx.x * blockDim.x + threadIdx.x;
    // zero output (2048 floats) from the first blocks
    for (int i = t; i < out_n; i += gridDim.x * blockDim.x) out[i] = 0.0f;

    int rc = 0;
    if (t < n_quads) {
        int4 b4 = ((const int4*)batch)[t];
        int4 z4 = ((const int4*)z)[t];
        rc = max(rc, atomicAdd(&g_cnt[b4.x], 1) + 1);
        rc = max(rc, atomicAdd(&g_cnt[b4.y], 1) + 1);
        rc = max(rc, atomicAdd(&g_cnt[b4.z], 1) + 1);
        rc = max(rc, atomicAdd(&g_cnt[b4.w], 1) + 1);
        ushort4 tag;
        tag.x = (unsigned short)((b4.x << 4) | z4.x);
        tag.y = (unsigned short)((b4.y << 4) | z4.y);
        tag.z = (unsigned short)((b4.z << 4) | z4.z);
        tag.w = (unsigned short)((b4.w << 4) | z4.w);
        ((ushort4*)g_bz)[t] = tag;
    }
    // tail atoms (n_atoms % 4)
    int e = n_quads * 4 + t;
    if (t < (n_atoms - n_quads * 4)) {
        int b = batch[e];
        g_bz[e] = (unsigned short)((b << 4) | z[e]);
        rc = max(rc, atomicAdd(&g_cnt[b], 1) + 1);
    }
    #pragma unroll
    for (int off = 16; off > 0; off >>= 1)
        rc = max(rc, __shfl_down_sync(0xffffffffu, rc, off));
    if ((threadIdx.x & 31) == 0 && rc > 0)
        atomicMax(&g_maxd, rc);
}

// Per-edge body: register-only prefilter |s-d| < D, then exact tag check,
// then rare-path physics (~0.15% of edges pass the prefilter).
#define EDGE_BODY(s, d)                                                        \
    do {                                                                       \
        if (abs((s) - (d)) < D) {                                              \
            unsigned short bs = __ldg(&g_bz[(s)]);                             \
            unsigned short bd = __ldg(&g_bz[(d)]);                             \
            if ((bs >> 4) == (bd >> 4)) {                                      \
                float dx = __ldg(&pos[3 * (s) + 0]) - __ldg(&pos[3 * (d) + 0]);\
                float dy = __ldg(&pos[3 * (s) + 1]) - __ldg(&pos[3 * (d) + 1]);\
                float dz = __ldg(&pos[3 * (s) + 2]) - __ldg(&pos[3 * (d) + 2]);\
                float d2 = dx * dx + dy * dy + dz * dz;                        \
                if (d2 <= 9.0f) {                                              \
                    float dist = fmaxf(sqrtf(d2), 1e-9f);                      \
                    float dau  = dist * 1.8897261258369282f;                   \
                    int zs = bs & 15, zd = bd & 15;                            \
                    float at  = sqrtf(__ldg(&arep[zs]) * __ldg(&arep[zd]));    \
                    float rep = __ldg(&zeff[zs]) * __ldg(&zeff[zd]) *          \
                                expf(-at * dau * sqrtf(dau)) / dau;            \
                    atomicAdd(&out[bs >> 4], rep * 627.5094740630558f);        \
                }                                                              \
            }                                                                  \
        }                                                                      \
    } while (0)

// Kernel 2: main edge stream, 4 edges/thread (round-4 proven config),
// streaming (.cs) loads for the never-reused edge index data.
// Last-arriving block resets device state for the next graph replay.
__global__ void __launch_bounds__(THREADS)
repulsion_kernel(const float* __restrict__ pos,
                 const float* __restrict__ arep,
                 const float* __restrict__ zeff,
                 const int*   __restrict__ src_idx,
                 const int*   __restrict__ dst_idx,
                 float*       __restrict__ out,
                 int n_quads,    // number of 4-edge quads
                 int n_rem)      // leftover edges (< 4)
{
    __shared__ int s_D;
    __shared__ int s_last;

    // Read D BEFORE joining the ticket, so the resetter can never clobber
    // g_maxd before this block has read it.
    if (threadIdx.x == 0) {
        s_D = g_maxd;
        int arrived = atomicAdd(&g_ready, 1);
        s_last = (arrived == (int)gridDim.x - 1);
    }
    __syncthreads();
    const int D = s_D > 0 ? s_D : 1;   // same-graph => |src-dst| < D (batch sorted)

    // Last block restores the zero state for the next replay.
    if (s_last) {
        for (int i = threadIdx.x; i < NUM_GRAPHS; i += THREADS) g_cnt[i] = 0;
        if (threadIdx.x == 0) { g_maxd = 0; g_ready = 0; }
    }

    int t = blockIdx.x * blockDim.x + threadIdx.x;
    if (t < n_quads) {
        // evict-first streaming loads: edge data is never reused
        int4 s4 = __ldcs(&((const int4*)src_idx)[t]);
        int4 d4 = __ldcs(&((const int4*)dst_idx)[t]);
        EDGE_BODY(s4.x, d4.x);
        EDGE_BODY(s4.y, d4.y);
        EDGE_BODY(s4.z, d4.z);
        EDGE_BODY(s4.w, d4.w);
    }

    // Scalar tail (edges not covered by quads)
    if (blockIdx.x == 0 && (int)threadIdx.x < n_rem) {
        int e = n_quads * 4 + threadIdx.x;
        int s = src_idx[e];
        int d = dst_idx[e];
        EDGE_BODY(s, d);
    }
}

extern "C" void kernel_launch(void* const* d_in, const int* in_sizes, int n_in,
                              void* d_out, int out_size) {
    const float* pos        = (const float*)d_in[0];
    const float* arep       = (const float*)d_in[1];
    const float* zeff       = (const float*)d_in[2];
    const int*   z          = (const int*)d_in[3];
    const int*   edge_index = (const int*)d_in[4];
    const int*   batch      = (const int*)d_in[5];
    float*       out        = (float*)d_out;

    int n_atoms = in_sizes[3];
    int n_edges = in_sizes[4] / 2;
    const int* src_idx = edge_index;
    const int* dst_idx = edge_index + n_edges;

    // 1) pack tags + zero output + max graph size
    int a_quads = n_atoms / 4;
    int pack_blocks = (a_quads + THREADS - 1) / THREADS;
    if (pack_blocks < 1) pack_blocks = 1;
    pack_tags_kernel<<<pack_blocks, THREADS>>>(z, batch, out, out_size,
                                               a_quads, n_atoms);

    // 2) main edge stream (4 edges/thread)
    int n_quads = n_edges / 4;
    int n_rem   = n_edges - n_quads * 4;
    int blocks  = (n_quads + THREADS - 1) / THREADS;
    if (blocks < 1) blocks = 1;
    repulsion_kernel<<<blocks, THREADS>>>(pos, arep, zeff, src_idx, dst_idx,
                                          out, n_quads, n_rem);
}

// round 17
// speedup vs baseline: 1.3474x; 1.0077x over previous
#include <cuda_runtime.h>
#include <cuda_bf16.h>

#define NUM_GRAPHS 2048
#define MAX_ATOMS  200000
#define THREADS    256

// Packed per-atom tag: (batch << 4) | z.  batch < 2048 (11 bits), z in 1..10 (4 bits).
// g_cnt/g_maxd/g_ready are zero at every kernel_launch entry (zero-init once,
// then restored by the edge kernel's last block on each launch).
__device__ unsigned short g_bz[MAX_ATOMS];
__device__ int g_cnt[NUM_GRAPHS];   // running atom counts per graph
__device__ int g_maxd;              // max graph size (prefilter radius)
__device__ int g_ready;             // edge-kernel arrival ticket (for state reset)

// Kernel 1: zero output + pack tags + max graph size.
// Running-count trick: max over i of (running count of batch[i]) == max graph size.
__global__ void pack_tags_kernel(const int* __restrict__ z,
                                 const int* __restrict__ batch,
                                 float* __restrict__ out, int out_n,
                                 int n_quads,    // n_atoms/4
                                 int n_atoms) {
    int t = blockIdx.x * blockDim.x + threadIdx.x;
    for (int i = t; i < out_n; i += gridDim.x * blockDim.x) out[i] = 0.0f;

    int rc = 0;
    if (t < n_quads) {
        int4 b4 = ((const int4*)batch)[t];
        int4 z4 = ((const int4*)z)[t];
        rc = max(rc, atomicAdd(&g_cnt[b4.x], 1) + 1);
        rc = max(rc, atomicAdd(&g_cnt[b4.y], 1) + 1);
        rc = max(rc, atomicAdd(&g_cnt[b4.z], 1) + 1);
        rc = max(rc, atomicAdd(&g_cnt[b4.w], 1) + 1);
        ushort4 tag;
        tag.x = (unsigned short)((b4.x << 4) | z4.x);
        tag.y = (unsigned short)((b4.y << 4) | z4.y);
        tag.z = (unsigned short)((b4.z << 4) | z4.z);
        tag.w = (unsigned short)((b4.w << 4) | z4.w);
        ((ushort4*)g_bz)[t] = tag;
    }
    int e = n_quads * 4 + t;
    if (t < (n_atoms - n_quads * 4)) {
        int b = batch[e];
        g_bz[e] = (unsigned short)((b << 4) | z[e]);
        rc = max(rc, atomicAdd(&g_cnt[b], 1) + 1);
    }
    #pragma unroll
    for (int off = 16; off > 0; off >>= 1)
        rc = max(rc, __shfl_down_sync(0xffffffffu, rc, off));
    if ((threadIdx.x & 31) == 0 && rc > 0)
        atomicMax(&g_maxd, rc);
}

// Rare-path per-edge body (invoked only when the quad-level prefilter fires):
// exact tag check, then physics (~0.15% of edges reach here).
#define EDGE_BODY(p, s, d)                                                     \
    do {                                                                       \
        if (p) {                                                               \
            unsigned short bs = __ldg(&g_bz[(s)]);                             \
            unsigned short bd = __ldg(&g_bz[(d)]);                             \
            if ((bs >> 4) == (bd >> 4)) {                                      \
                float dx = __ldg(&pos[3 * (s) + 0]) - __ldg(&pos[3 * (d) + 0]);\
                float dy = __ldg(&pos[3 * (s) + 1]) - __ldg(&pos[3 * (d) + 1]);\
                float dz = __ldg(&pos[3 * (s) + 2]) - __ldg(&pos[3 * (d) + 2]);\
                float d2 = dx * dx + dy * dy + dz * dz;                        \
                if (d2 <= 9.0f) {                                              \
                    float dist = fmaxf(sqrtf(d2), 1e-9f);                      \
                    float dau  = dist * 1.8897261258369282f;                   \
                    int zs = bs & 15, zd = bd & 15;                            \
                    float at  = sqrtf(__ldg(&arep[zs]) * __ldg(&arep[zd]));    \
                    float rep = __ldg(&zeff[zs]) * __ldg(&zeff[zd]) *          \
                                expf(-at * dau * sqrtf(dau)) / dau;            \
                    atomicAdd(&out[bs >> 4], rep * 627.5094740630558f);        \
                }                                                              \
            }                                                                  \
        }                                                                      \
    } while (0)

// Kernel 2: main edge stream, 4 edges/thread, single fused prefilter branch
// per quad (99.4% of threads take zero edges -> one not-taken branch).
// Last-arriving block resets device state for the next graph replay.
__global__ void __launch_bounds__(THREADS)
repulsion_kernel(const float* __restrict__ pos,
                 const float* __restrict__ arep,
                 const float* __restrict__ zeff,
                 const int*   __restrict__ src_idx,
                 const int*   __restrict__ dst_idx,
                 float*       __restrict__ out,
                 int n_quads,    // number of 4-edge quads
                 int n_rem)      // leftover edges (< 4)
{
    __shared__ int s_D;
    __shared__ int s_last;

    // Read D BEFORE joining the ticket, so the resetter can never clobber
    // g_maxd before this block has read it.
    if (threadIdx.x == 0) {
        s_D = g_maxd;
        int arrived = atomicAdd(&g_ready, 1);
        s_last = (arrived == (int)gridDim.x - 1);
    }
    __syncthreads();
    const int D = s_D > 0 ? s_D : 1;   // same-graph => |src-dst| < D (batch sorted)

    // Last block restores the zero state for the next replay.
    if (s_last) {
        for (int i = threadIdx.x; i < NUM_GRAPHS; i += THREADS) g_cnt[i] = 0;
        if (threadIdx.x == 0) { g_maxd = 0; g_ready = 0; }
    }

    int t = blockIdx.x * blockDim.x + threadIdx.x;
    if (t < n_quads) {
        int4 s4 = ((const int4*)src_idx)[t];
        int4 d4 = ((const int4*)dst_idx)[t];
        // branchless predicates, one combined branch for the whole quad
        bool p0 = abs(s4.x - d4.x) < D;
        bool p1 = abs(s4.y - d4.y) < D;
        bool p2 = abs(s4.z - d4.z) < D;
        bool p3 = abs(s4.w - d4.w) < D;
        if (p0 | p1 | p2 | p3) {
            EDGE_BODY(p0, s4.x, d4.x);
            EDGE_BODY(p1, s4.y, d4.y);
            EDGE_BODY(p2, s4.z, d4.z);
            EDGE_BODY(p3, s4.w, d4.w);
        }
    }

    // Scalar tail (edges not covered by quads)
    if (blockIdx.x == 0 && (int)threadIdx.x < n_rem) {
        int e = n_quads * 4 + threadIdx.x;
        int s = src_idx[e];
        int d = dst_idx[e];
        bool p = abs(s - d) < D;
        EDGE_BODY(p, s, d);
    }
}

extern "C" void kernel_launch(void* const* d_in, const int* in_sizes, int n_in,
                              void* d_out, int out_size) {
    const float* pos        = (const float*)d_in[0];
    const float* arep       = (const float*)d_in[1];
    const float* zeff       = (const float*)d_in[2];
    const int*   z          = (const int*)d_in[3];
    const int*   edge_index = (const int*)d_in[4];
    const int*   batch      = (const int*)d_in[5];
    float*       out        = (float*)d_out;

    int n_atoms = in_sizes[3];
    int n_edges = in_sizes[4] / 2;
    const int* src_idx = edge_index;
    const int* dst_idx = edge_index + n_edges;

    // 1) pack tags + zero output + max graph size
    int a_quads = n_atoms / 4;
    int pack_blocks = (a_quads + THREADS - 1) / THREADS;
    if (pack_blocks < 1) pack_blocks = 1;
    pack_tags_kernel<<<pack_blocks, THREADS>>>(z, batch, out, out_size,
                                               a_quads, n_atoms);

    // 2) main edge stream (4 edges/thread, plain loads)
    int n_quads = n_edges / 4;
    int n_rem   = n_edges - n_quads * 4;
    int blocks  = (n_quads + THREADS - 1) / THREADS;
    if (blocks < 1) blocks = 1;
    repulsion_kernel<<<blocks, THREADS>>>(pos, arep, zeff, src_idx, dst_idx,
                                          out, n_quads, n_rem);
}